// round 14
// baseline (speedup 1.0000x reference)
#include <cuda_runtime.h>
#include <cuda_fp16.h>
#include <cstdint>

#define EPS   1e-5f
#define SLOPE 0.01f

__constant__ int c_SZ[4] = {1, 2, 3, 6};
__constant__ int c_S2[4] = {1, 4, 9, 36};
__constant__ int c_PO[4] = {0, 1, 5, 14};

// scratch (static device globals; no allocation)
__device__ float g_pool[204800];
__device__ float g_bo[51200];
__device__ float g_bhat[51200];
__device__ float g_v[4194304];
__device__ float g_scale[512];
__device__ float g_shift[512];
// pre-swizzled FP16 operands (32-bit words = half2 of channel pairs)
__device__ uint32_t g_wA[4980736];    // [4 ot][128 chunk][128 o][76 words]
__device__ uint32_t g_fB[10747904];   // [32 nb][128 chunk][8 pair][328 words]

// ---------------------------------------------------------------- helpers
__device__ __forceinline__ uint32_t smem_u32(const void* p) {
    uint32_t a;
    asm("{ .reg .u64 t; cvta.to.shared.u64 t, %1; cvt.u32.u64 %0, t; }" : "=r"(a) : "l"(p));
    return a;
}
__device__ __forceinline__ void cp16(uint32_t dst, const void* src) {
    asm volatile("cp.async.cg.shared.global [%0], [%1], 16;" :: "r"(dst), "l"(src));
}
__device__ __forceinline__ void cp_commit() {
    asm volatile("cp.async.commit_group;" ::: "memory");
}
template <int N> __device__ __forceinline__ void cp_wait() {
    asm volatile("cp.async.wait_group %0;" :: "n"(N) : "memory");
}
__device__ __forceinline__ void mma16(float* c, uint32_t a0, uint32_t a1, uint32_t a2, uint32_t a3,
                                      uint32_t b0, uint32_t b1) {
    asm volatile("mma.sync.aligned.m16n8k16.row.col.f32.f16.f16.f32 "
                 "{%0,%1,%2,%3}, {%4,%5,%6,%7}, {%8,%9}, {%0,%1,%2,%3};\n"
                 : "+f"(c[0]), "+f"(c[1]), "+f"(c[2]), "+f"(c[3])
                 : "r"(a0), "r"(a1), "r"(a2), "r"(a3), "r"(b0), "r"(b1));
}
__device__ __forceinline__ void ldsm4(uint32_t& r0, uint32_t& r1, uint32_t& r2, uint32_t& r3,
                                      uint32_t addr) {
    asm volatile("ldmatrix.sync.aligned.m8n8.x4.shared.b16 {%0,%1,%2,%3}, [%4];"
                 : "=r"(r0), "=r"(r1), "=r"(r2), "=r"(r3) : "r"(addr));
}

// ------------------- pools via row prefix sums (+ zero g_bo in blocks <50)
__global__ void k_pool(const float* __restrict__ feats) {
    __shared__ float S[64][65];
    __shared__ float rowp[768];
    int nc = blockIdx.x;
    int tid = threadIdx.x;
    if (nc < 50) {
        for (int i = tid; i < 1024; i += 256) g_bo[nc * 1024 + i] = 0.f;
    }
    const float* src = feats + (size_t)nc * 4096;
    int warp = tid >> 5, lane = tid & 31;
    #pragma unroll
    for (int k = 0; k < 8; k++) {
        int y = warp * 8 + k;
        float v = src[y * 64 + lane];
        #pragma unroll
        for (int off = 1; off < 32; off <<= 1) {
            float n = __shfl_up_sync(0xffffffffu, v, off);
            if (lane >= off) v += n;
        }
        float tot = __shfl_sync(0xffffffffu, v, 31);
        float w = src[y * 64 + 32 + lane];
        #pragma unroll
        for (int off = 1; off < 32; off <<= 1) {
            float n = __shfl_up_sync(0xffffffffu, w, off);
            if (lane >= off) w += n;
        }
        S[y][lane + 1] = v;
        S[y][lane + 33] = w + tot;
        if (lane == 0) S[y][0] = 0.f;
    }
    __syncthreads();
    for (int t = tid; t < 768; t += 256) {
        int b, loc;
        if (t < 64)       { b = 0; loc = t; }
        else if (t < 192) { b = 1; loc = t - 64; }
        else if (t < 384) { b = 2; loc = t - 192; }
        else              { b = 3; loc = t - 384; }
        int s = c_SZ[b];
        int y = loc / s, j = loc - y * s;
        int xs = (j * 64) / s, xe = ((j + 1) * 64 + s - 1) / s;
        rowp[t] = S[y][xe] - S[y][xs];
    }
    __syncthreads();
    if (tid < 50) {
        int t = tid; int b, loc;
        if (t < 1)       { b = 0; loc = 0; }
        else if (t < 5)  { b = 1; loc = t - 1; }
        else if (t < 14) { b = 2; loc = t - 5; }
        else             { b = 3; loc = t - 14; }
        int s = c_SZ[b];
        int i = loc / s, j = loc - i * s;
        int ys = (i * 64) / s, ye = ((i + 1) * 64 + s - 1) / s;
        int xs = (j * 64) / s, xe = ((j + 1) * 64 + s - 1) / s;
        int rb = (b == 0) ? 0 : (b == 1) ? 64 : (b == 2) ? 192 : 384;
        float a = 0.f;
        for (int y = ys; y < ye; y++) a += rowp[rb + y * s + j];
        g_pool[c_PO[b] * 4096 + nc * c_S2[b] + loc] = a / (float)((ye - ys) * (xe - xs));
    }
}

// ----------------------- fused 1x1 convs: templated bodies, split-K 64
template <int S2>
__device__ __forceinline__ void conv1f_body(const float* __restrict__ W) {
    extern __shared__ float sm[];
    constexpr int C = 2 * S2;
    constexpr int Cp = C + 1;
    constexpr int PO = (S2 == 1) ? 0 : (S2 == 4) ? 1 : (S2 == 9) ? 5 : 14;
    constexpr int NA = (C + 3) / 4;
    float* pc = sm;
    float* ws = sm + 64 * Cp;
    int o0 = blockIdx.y * 64;
    int c0 = blockIdx.x * 64;
    int tid = threadIdx.x;
    int o = tid >> 2, grp = tid & 3;

    for (int i = tid; i < 64 * C; i += 256) {
        int c = i / C, col = i - c * C;
        int n = col / S2, ij = col - n * S2;
        pc[c * Cp + col] = g_pool[PO * 4096 + (n * 2048 + c0 + c) * S2 + ij];
    }
    for (int i = tid; i < 4096; i += 256) {
        int oo = i >> 6, k = i & 63;
        ws[oo * 65 + k] = W[(size_t)(o0 + oo) * 2048 + c0 + k];
    }
    __syncthreads();

    float acc[NA];
    #pragma unroll
    for (int a = 0; a < NA; a++) acc[a] = 0.f;
    for (int c = 0; c < 64; c++) {
        float w = ws[o * 65 + c];
        const float* pr = &pc[c * Cp];
        #pragma unroll
        for (int a = 0; a < NA; a++) {
            int col = grp + 4 * a;
            if (col < C) acc[a] += w * pr[col];
        }
    }
    #pragma unroll
    for (int a = 0; a < NA; a++) {
        int col = grp + 4 * a;
        if (col < C) {
            int n = col / S2, ij = col - n * S2;
            atomicAdd(&g_bo[PO * 1024 + (n * 512 + o0 + o) * S2 + ij], acc[a]);
        }
    }
}

__global__ void k_conv1f(const float* __restrict__ w0, const float* __restrict__ w1,
                         const float* __restrict__ w2, const float* __restrict__ w3) {
    switch (blockIdx.z) {
        case 0:  conv1f_body<1>(w0);  break;
        case 1:  conv1f_body<4>(w1);  break;
        case 2:  conv1f_body<9>(w2);  break;
        default: conv1f_body<36>(w3); break;
    }
}

// ---------------------------------------- per-branch BN + lrelu
__global__ void k_bnbr(const float* __restrict__ g0, const float* __restrict__ b0,
                       const float* __restrict__ g1, const float* __restrict__ b1,
                       const float* __restrict__ g2, const float* __restrict__ b2,
                       const float* __restrict__ g3, const float* __restrict__ b3) {
    int b = blockIdx.x >> 9, o = blockIdx.x & 511;
    int s2 = c_S2[b], cnt = 2 * s2;
    int tid = threadIdx.x;
    __shared__ float rs[128], rq[128];
    float v = 0.f; int idx = 0;
    if (tid < cnt) {
        int n = tid / s2, ij = tid - n * s2;
        idx = c_PO[b] * 1024 + (n * 512 + o) * s2 + ij;
        v = g_bo[idx];
    }
    rs[tid] = (tid < cnt) ? v : 0.f;
    rq[tid] = (tid < cnt) ? v * v : 0.f;
    __syncthreads();
    for (int st = 64; st > 0; st >>= 1) {
        if (tid < st) { rs[tid] += rs[tid + st]; rq[tid] += rq[tid + st]; }
        __syncthreads();
    }
    float mean = rs[0] / cnt, var = rq[0] / cnt - mean * mean;
    const float* gp = (b == 0) ? g0 : (b == 1) ? g1 : (b == 2) ? g2 : g3;
    const float* bp = (b == 0) ? b0 : (b == 1) ? b1 : (b == 2) ? b2 : b3;
    float sc = gp[o] * rsqrtf(var + EPS);
    float sh = bp[o] - mean * sc;
    if (tid < cnt) {
        float y = v * sc + sh;
        g_bhat[idx] = (y >= 0.f) ? y : SLOPE * y;
    }
}

// ===== fused q-GEMM + H-upsample + W-upsample -> g_v. block = one o (512). ==
#define QUPSV_SMEM (17408 * 4)
__global__ __launch_bounds__(512, 1) void k_qupsv(const float* __restrict__ wb) {
    extern __shared__ float sm[];
    float* ws = sm;
    float* bs = sm + 4608;
    int o = blockIdx.x;
    int tid = threadIdx.x;

    int tb, ttap = 0, tij = 0, ts2 = 1, tbase = 0;
    {
        int t = tid;
        if (t < 9)        { tb = 0; tbase = 0; }
        else if (t < 45)  { tb = 1; tbase = 9; }
        else if (t < 126) { tb = 2; tbase = 45; }
        else if (t < 450) { tb = 3; tbase = 126; }
        else              { tb = -1; }
        if (tb >= 0) {
            ts2 = c_S2[tb];
            int loc = t - tbase;
            ttap = loc / ts2; tij = loc - ttap * ts2;
        }
    }
    float acc0 = 0.f, acc1 = 0.f;
    const float* wrow = wb + (size_t)o * 36864;

    int bsOff[4] = {0, 256, 1280, 3584};
    for (int cc = 0; cc < 512; cc += 128) {
        __syncthreads();
        for (int i = tid; i < 4608; i += 512) {
            int b = (i < 1152) ? 0 : (i < 2304) ? 1 : (i < 3456) ? 2 : 3;
            int rr = i - b * 1152;
            ws[i] = wrow[b * 4608 + cc * 9 + rr];
        }
        for (int i = tid; i < 12800; i += 512) {
            int idx;
            if (i < 256) {
                int n = i >> 7, r = i & 127;
                idx = (n * 512 + cc + r);
            } else if (i < 1280) {
                int loc = i - 256;
                int n = loc >> 9, r = loc & 511;
                int c = r >> 2, ij = r & 3;
                idx = 1024 + (n * 512 + cc + c) * 4 + ij;
            } else if (i < 3584) {
                int loc = i - 1280;
                int n = loc / 1152, r = loc - n * 1152;
                int c = r / 9, ij = r - c * 9;
                idx = 5120 + (n * 512 + cc + c) * 9 + ij;
            } else {
                int loc = i - 3584;
                int n = loc / 4608, r = loc - n * 4608;
                int c = r / 36, ij = r - c * 36;
                idx = 14336 + (n * 512 + cc + c) * 36 + ij;
            }
            bs[i] = g_bhat[idx];
        }
        __syncthreads();
        if (tb >= 0) {
            const float* wv = &ws[tb * 1152 + ttap];
            const float* b0 = &bs[bsOff[tb] + tij];
            const float* b1 = b0 + 128 * ts2;
            #pragma unroll 8
            for (int c = 0; c < 128; c++) {
                float w = wv[c * 9];
                acc0 += w * b0[c * ts2];
                acc1 += w * b1[c * ts2];
            }
        }
    }
    __syncthreads();
    float* q2 = sm;
    float* u2 = sm + 1024;
    if (tb >= 0) {
        int qi = tbase + ttap * ts2 + tij;
        q2[qi] = acc0;
        q2[456 + qi] = acc1;
    }
    __syncthreads();

    for (int t = tid; t < 4608; t += 512) {
        int n = t / 2304, loc = t - n * 2304;
        int b, lb, ub;
        if (loc < 192)       { b = 0; lb = loc;        ub = 0; }
        else if (loc < 576)  { b = 1; lb = loc - 192;  ub = 192; }
        else if (loc < 1152) { b = 2; lb = loc - 576;  ub = 576; }
        else                 { b = 3; lb = loc - 1152; ub = 1152; }
        int s = c_SZ[b], s2 = c_S2[b];
        int kx = lb / (64 * s); int rem = lb - kx * 64 * s;
        int y = rem / s, j = rem - y * s;
        int qb = n * 456 + ((b == 0) ? 0 : (b == 1) ? 9 : (b == 2) ? 45 : 126);
        float fs = (s > 1) ? (float)(s - 1) / 63.0f : 0.0f;
        float a = 0.f;
        #pragma unroll
        for (int ky = 0; ky < 3; ky++) {
            int Y = y + ky - 1;
            if (Y < 0 || Y > 63) continue;
            float pos = Y * fs;
            int i0 = (int)pos; float w = pos - i0; int i1 = min(i0 + 1, s - 1);
            const float* qq = &q2[qb + (ky * 3 + kx) * s2 + j];
            a += (1.f - w) * qq[i0 * s] + w * qq[i1 * s];
        }
        u2[n * 2304 + ub + kx * 64 * s + y * s + j] = a;
    }
    __syncthreads();

    for (int t = tid; t < 8192; t += 512) {
        int n = t >> 12, px = t & 4095;
        int y = px >> 6, x = px & 63;
        float a = 0.f;
        #pragma unroll
        for (int b = 0; b < 4; b++) {
            int s = c_SZ[b];
            int ub = (b == 0) ? 0 : (b == 1) ? 192 : (b == 2) ? 576 : 1152;
            float fs = (s > 1) ? (float)(s - 1) / 63.f : 0.f;
            #pragma unroll
            for (int kx = 0; kx < 3; kx++) {
                int X = x + kx - 1;
                if (X < 0 || X > 63) continue;
                float pos = X * fs;
                int j0 = (int)pos; float w = pos - j0; int j1 = min(j0 + 1, s - 1);
                const float* uu = &u2[n * 2304 + ub + (kx * 64 + y) * s];
                a += (1.f - w) * uu[j0] + w * uu[j1];
            }
        }
        g_v[(((size_t)(n * 512 + o)) << 12) + px] = a;
    }
}

// ----------------- merged prep: blocks [0,512) = weights, [512,4608) = patches
__global__ void k_prep(const float* __restrict__ wb, const float* __restrict__ feats) {
    int tid = threadIdx.x;
    if (blockIdx.x < 512) {
        __shared__ float buf[32][148];
        int bx = blockIdx.x;
        int ot = bx >> 7, j = bx & 127;
        for (int g = 0; g < 4; g++) {
            __syncthreads();
            for (int i = tid; i < 1152; i += 512) {
                int ol = i / 36, f4 = i - ol * 36;
                const float4 v = *reinterpret_cast<const float4*>(
                    wb + (size_t)(ot * 128 + g * 32 + ol) * 36864 + 18432 + j * 144 + f4 * 4);
                buf[ol][f4 * 4] = v.x; buf[ol][f4 * 4 + 1] = v.y;
                buf[ol][f4 * 4 + 2] = v.z; buf[ol][f4 * 4 + 3] = v.w;
            }
            __syncthreads();
            for (int i = tid; i < 2432; i += 512) {
                int ol = i / 76, r = i - ol * 76;
                uint32_t val = 0u;
                if (r < 72) {
                    int tap = r >> 3, p = r & 7;
                    __half2 h = __floats2half2_rn(buf[ol][2 * p * 9 + tap],
                                                  buf[ol][(2 * p + 1) * 9 + tap]);
                    val = *reinterpret_cast<uint32_t*>(&h);
                }
                g_wA[(size_t)bx * 9728 + (g * 32 + ol) * 76 + r] = val;
            }
        }
    } else {
        int bx = blockIdx.x - 512;     // = nb*128 + j
        int nb = bx >> 7, j = bx & 127;
        int n = nb >> 4, t = nb & 15;
        int ty0 = (t >> 2) * 16, tx0 = (t & 3) * 16;
        size_t dbase = (size_t)bx * 2624;
        for (int i = tid; i < 2592; i += 512) {
            int p = i / 324, rr = i - p * 324;
            int y = rr / 18, x = rr - y * 18;
            int gy = ty0 + y - 1, gx = tx0 + x - 1;
            uint32_t val = 0u;
            if ((unsigned)gy < 64u && (unsigned)gx < 64u) {
                int c = j * 16 + 2 * p;
                const float* s = feats + (((size_t)(n * 2048 + c)) << 12) + (gy << 6) + gx;
                __half2 h = __floats2half2_rn(s[0], s[4096]);
                val = *reinterpret_cast<uint32_t*>(&h);
            }
            g_fB[dbase + p * 328 + rr] = val;
        }
    }
}

// ======================= conv3x3: FP16 mma + ldmatrix, batched frags =======
#define ABYTES  38912u
#define PBYTES  10496u
#define STAGEB  49408u
#define NCP     3088
#define NCPA    2432
#define CONV_SMEM (3 * STAGEB)   // 148224

__global__ __launch_bounds__(512, 1) void k_conv3_h(float* __restrict__ out) {
    extern __shared__ char smem[];
    uint32_t sb = smem_u32(smem);
    int tid = threadIdx.x;
    int warp = tid >> 5, lane = tid & 31;
    int bx = blockIdx.x;
    int nb = blockIdx.y;
    int o0 = bx * 128;
    int n2 = nb >> 4;
    int t = nb & 15;
    int ty0 = (t >> 2) * 16, tx0 = (t & 3) * 16;
    int wm = warp >> 3, wn = warp & 7;
    int gid = lane >> 2, tig = lane & 3;
    int rsel = (lane & 8) + (lane & 7);
    int koff = (lane & 16) ? 4 : 0;

    float acc[4][4][4];
    #pragma unroll
    for (int mi = 0; mi < 4; mi++)
        #pragma unroll
        for (int ni = 0; ni < 4; ni++)
            #pragma unroll
            for (int r = 0; r < 4; r++) acc[mi][ni][r] = 0.f;

    int py[4], px[4];
    #pragma unroll
    for (int ni = 0; ni < 4; ni++) {
        int p = wn * 32 + ni * 8 + gid;
        py[ni] = p >> 4; px[ni] = p & 15;
    }

    const char* srcAbase = (const char*)(g_wA + (size_t)bx * 128 * 9728);
    const char* srcPbase = (const char*)(g_fB + (size_t)nb * 128 * 2624);

    auto stage = [&](int j) {
        uint32_t dA = sb + (j % 3) * STAGEB;
        uint32_t dP = dA + ABYTES;
        const char* sA = srcAbase + (size_t)j * ABYTES;
        const char* sP = srcPbase + (size_t)j * PBYTES;
        for (int i = tid; i < NCP; i += 512) {
            if (i < NCPA) cp16(dA + i * 16, sA + i * 16);
            else          cp16(dP + (i - NCPA) * 16, sP + (size_t)(i - NCPA) * 16);
        }
        cp_commit();
    };

    stage(0);
    stage(1);

    for (int j = 0; j < 128; j++) {
        if (j < 127) cp_wait<1>(); else cp_wait<0>();
        __syncthreads();
        if (j + 2 < 128) stage(j + 2);

        uint32_t aBase = sb + (j % 3) * STAGEB;
        const uint32_t* Ps = (const uint32_t*)(smem + (j % 3) * STAGEB + ABYTES);

        #pragma unroll
        for (int ky = 0; ky < 3; ky++) {
            #pragma unroll
            for (int kx = 0; kx < 3; kx++) {
                int tap8 = (ky * 3 + kx) * 8;
                // batch ALL independent loads for this tap first (max MLP)
                uint32_t A[4][4];
                uint32_t bf[4][2];
                #pragma unroll
                for (int mi = 0; mi < 4; mi++) {
                    int m0 = wm * 64 + mi * 16;
                    ldsm4(A[mi][0], A[mi][1], A[mi][2], A[mi][3],
                          aBase + (uint32_t)(((m0 + rsel) * 76 + tap8 + koff) * 4));
                }
                #pragma unroll
                for (int ni = 0; ni < 4; ni++) {
                    int off = (py[ni] + ky) * 18 + px[ni] + kx;
                    bf[ni][0] = Ps[tig * 328 + off];
                    bf[ni][1] = Ps[(tig + 4) * 328 + off];
                }
                // dependent MMA burst
                #pragma unroll
                for (int mi = 0; mi < 4; mi++)
                    #pragma unroll
                    for (int ni = 0; ni < 4; ni++)
                        mma16(acc[mi][ni], A[mi][0], A[mi][1], A[mi][2], A[mi][3],
                              bf[ni][0], bf[ni][1]);
            }
        }
        __syncthreads();
    }

    // epilogue: store raw conv output (g_v folded into stats/apply)
    #pragma unroll
    for (int mi = 0; mi < 4; mi++) {
        int oa = o0 + wm * 64 + mi * 16 + gid;
        #pragma unroll
        for (int ni = 0; ni < 4; ni++) {
            int pA = wn * 32 + ni * 8 + 2 * tig;
            #pragma unroll
            for (int r = 0; r < 4; r++) {
                int o = oa + ((r >= 2) ? 8 : 0);
                int p = pA + (r & 1);
                int yy = ty0 + (p >> 4), xx = tx0 + (p & 15);
                size_t gi = (((size_t)(n2 * 512 + o)) << 12) + (yy << 6) + xx;
                out[gi] = acc[mi][ni][r];
            }
        }
    }
}

// ----------------------------------------------- final BN stats (z = out+v)
__global__ void k_stats(const float* __restrict__ z, const float* __restrict__ gb,
                        const float* __restrict__ bbp) {
    int o = blockIdx.x;
    int tid = threadIdx.x;
    float s = 0.f, sq = 0.f;
    for (int n = 0; n < 2; n++) {
        size_t base = ((size_t)(n * 512 + o)) << 10;
        const float4* p = (const float4*)z + base;
        const float4* pv = (const float4*)g_v + base;
        for (int i = tid; i < 1024; i += 256) {
            float4 a = p[i], b = pv[i];
            float v0 = a.x + b.x, v1 = a.y + b.y, v2 = a.z + b.z, v3 = a.w + b.w;
            s += v0 + v1 + v2 + v3;
            sq += v0 * v0 + v1 * v1 + v2 * v2 + v3 * v3;
        }
    }
    __shared__ float rs[256], rq[256];
    rs[tid] = s; rq[tid] = sq; __syncthreads();
    for (int st = 128; st > 0; st >>= 1) {
        if (tid < st) { rs[tid] += rs[tid + st]; rq[tid] += rq[tid + st]; }
        __syncthreads();
    }
    if (tid == 0) {
        float mean = rs[0] * (1.f / 8192.f);
        float var = rq[0] * (1.f / 8192.f) - mean * mean;
        float sc = gb[o] * rsqrtf(var + EPS);
        g_scale[o] = sc;
        g_shift[o] = bbp[o] - mean * sc;
    }
}

// ----------------------------------------------- apply BN + lrelu (z = out+v)
__global__ void k_apply(float* __restrict__ out) {
    int idx = blockIdx.x * 256 + threadIdx.x;
    if (idx >= 1048576) return;
    int o = (idx >> 10) & 511;
    float sc = g_scale[o], sh = g_shift[o];
    float4 a = ((const float4*)out)[idx];
    float4 b = ((const float4*)g_v)[idx];
    float z0 = (a.x + b.x) * sc + sh;
    float z1 = (a.y + b.y) * sc + sh;
    float z2 = (a.z + b.z) * sc + sh;
    float z3 = (a.w + b.w) * sc + sh;
    float4 r;
    r.x = (z0 >= 0.f) ? z0 : SLOPE * z0;
    r.y = (z1 >= 0.f) ? z1 : SLOPE * z1;
    r.z = (z2 >= 0.f) ? z2 : SLOPE * z2;
    r.w = (z3 >= 0.f) ? z3 : SLOPE * z3;
    ((float4*)out)[idx] = r;
}

extern "C" void kernel_launch(void* const* d_in, const int* in_sizes, int n_in,
                              void* d_out, int out_size) {
    const float* feats = (const float*)d_in[0];
    const float* w0 = (const float*)d_in[1];
    const float* g0 = (const float*)d_in[2];
    const float* b0 = (const float*)d_in[3];
    const float* w1 = (const float*)d_in[4];
    const float* g1 = (const float*)d_in[5];
    const float* b1 = (const float*)d_in[6];
    const float* w2 = (const float*)d_in[7];
    const float* g2 = (const float*)d_in[8];
    const float* b2 = (const float*)d_in[9];
    const float* w3 = (const float*)d_in[10];
    const float* g3 = (const float*)d_in[11];
    const float* b3 = (const float*)d_in[12];
    const float* wb = (const float*)d_in[13];
    const float* gb = (const float*)d_in[14];
    const float* bb = (const float*)d_in[15];
    float* out = (float*)d_out;

    static cudaStream_t s3 = nullptr;
    static cudaEvent_t evFork = nullptr, evJoin = nullptr;
    static bool init_done = false;
    if (!init_done) {
        cudaFuncSetAttribute(k_conv3_h, cudaFuncAttributeMaxDynamicSharedMemorySize, CONV_SMEM);
        cudaFuncSetAttribute(k_qupsv, cudaFuncAttributeMaxDynamicSharedMemorySize, QUPSV_SMEM);
        cudaFuncSetAttribute(k_conv1f, cudaFuncAttributeMaxDynamicSharedMemorySize, 36000);
        cudaStreamCreateWithFlags(&s3, cudaStreamNonBlocking);
        cudaEventCreateWithFlags(&evFork, cudaEventDisableTiming);
        cudaEventCreateWithFlags(&evJoin, cudaEventDisableTiming);
        init_done = true;
    }

    // Fork arm B
    cudaEventRecord(evFork, 0);
    cudaStreamWaitEvent(s3, evFork, 0);

    // Arm A (stream 0): merged prep -> conv3
    k_prep<<<4608, 512>>>(wb, feats);
    k_conv3_h<<<dim3(4, 32), 512, CONV_SMEM>>>(out);

    // Arm B (s3): pool -> conv1f -> bnbr -> qupsv
    k_pool<<<4096, 256, 0, s3>>>(feats);
    k_conv1f<<<dim3(32, 8, 4), 256, 35400, s3>>>(w0, w1, w2, w3);
    k_bnbr<<<2048, 128, 0, s3>>>(g0, b0, g1, b1, g2, b2, g3, b3);
    k_qupsv<<<512, 512, QUPSV_SMEM, s3>>>(wb);
    cudaEventRecord(evJoin, s3);

    // Join, then fused BN over z = out + g_v
    cudaStreamWaitEvent(0, evJoin, 0);
    k_stats<<<512, 256>>>(out, gb, bb);
    k_apply<<<4096, 256>>>(out);
}

// round 15
// speedup vs baseline: 1.0254x; 1.0254x over previous
#include <cuda_runtime.h>
#include <cuda_fp16.h>
#include <cstdint>

#define EPS   1e-5f
#define SLOPE 0.01f

__constant__ int c_SZ[4] = {1, 2, 3, 6};
__constant__ int c_S2[4] = {1, 4, 9, 36};
__constant__ int c_PO[4] = {0, 1, 5, 14};

// scratch (static device globals; no allocation)
__device__ float g_pool[204800];
__device__ float g_bo[51200];
__device__ float g_bhat[51200];
__device__ float g_v[4194304];
// pre-swizzled FP16 operands (32-bit words = half2 of channel pairs)
__device__ uint32_t g_wA[4980736];    // [4 ot][128 chunk][128 o][76 words]
__device__ uint32_t g_fB[10747904];   // [32 nb][128 chunk][8 pair][328 words]

// ---------------------------------------------------------------- helpers
__device__ __forceinline__ uint32_t smem_u32(const void* p) {
    uint32_t a;
    asm("{ .reg .u64 t; cvta.to.shared.u64 t, %1; cvt.u32.u64 %0, t; }" : "=r"(a) : "l"(p));
    return a;
}
__device__ __forceinline__ void cp16(uint32_t dst, const void* src) {
    asm volatile("cp.async.cg.shared.global [%0], [%1], 16;" :: "r"(dst), "l"(src));
}
__device__ __forceinline__ void cp_commit() {
    asm volatile("cp.async.commit_group;" ::: "memory");
}
template <int N> __device__ __forceinline__ void cp_wait() {
    asm volatile("cp.async.wait_group %0;" :: "n"(N) : "memory");
}
__device__ __forceinline__ void mma16(float* c, uint32_t a0, uint32_t a1, uint32_t a2, uint32_t a3,
                                      uint32_t b0, uint32_t b1) {
    asm volatile("mma.sync.aligned.m16n8k16.row.col.f32.f16.f16.f32 "
                 "{%0,%1,%2,%3}, {%4,%5,%6,%7}, {%8,%9}, {%0,%1,%2,%3};\n"
                 : "+f"(c[0]), "+f"(c[1]), "+f"(c[2]), "+f"(c[3])
                 : "r"(a0), "r"(a1), "r"(a2), "r"(a3), "r"(b0), "r"(b1));
}
__device__ __forceinline__ void ldsm4(uint32_t& r0, uint32_t& r1, uint32_t& r2, uint32_t& r3,
                                      uint32_t addr) {
    asm volatile("ldmatrix.sync.aligned.m8n8.x4.shared.b16 {%0,%1,%2,%3}, [%4];"
                 : "=r"(r0), "=r"(r1), "=r"(r2), "=r"(r3) : "r"(addr));
}

// ------------------- pools via row prefix sums (+ zero g_bo in blocks <50)
__global__ void k_pool(const float* __restrict__ feats) {
    __shared__ float S[64][65];
    __shared__ float rowp[768];
    int nc = blockIdx.x;
    int tid = threadIdx.x;
    if (nc < 50) {
        for (int i = tid; i < 1024; i += 256) g_bo[nc * 1024 + i] = 0.f;
    }
    const float* src = feats + (size_t)nc * 4096;
    int warp = tid >> 5, lane = tid & 31;
    #pragma unroll
    for (int k = 0; k < 8; k++) {
        int y = warp * 8 + k;
        float v = src[y * 64 + lane];
        #pragma unroll
        for (int off = 1; off < 32; off <<= 1) {
            float n = __shfl_up_sync(0xffffffffu, v, off);
            if (lane >= off) v += n;
        }
        float tot = __shfl_sync(0xffffffffu, v, 31);
        float w = src[y * 64 + 32 + lane];
        #pragma unroll
        for (int off = 1; off < 32; off <<= 1) {
            float n = __shfl_up_sync(0xffffffffu, w, off);
            if (lane >= off) w += n;
        }
        S[y][lane + 1] = v;
        S[y][lane + 33] = w + tot;
        if (lane == 0) S[y][0] = 0.f;
    }
    __syncthreads();
    for (int t = tid; t < 768; t += 256) {
        int b, loc;
        if (t < 64)       { b = 0; loc = t; }
        else if (t < 192) { b = 1; loc = t - 64; }
        else if (t < 384) { b = 2; loc = t - 192; }
        else              { b = 3; loc = t - 384; }
        int s = c_SZ[b];
        int y = loc / s, j = loc - y * s;
        int xs = (j * 64) / s, xe = ((j + 1) * 64 + s - 1) / s;
        rowp[t] = S[y][xe] - S[y][xs];
    }
    __syncthreads();
    if (tid < 50) {
        int t = tid; int b, loc;
        if (t < 1)       { b = 0; loc = 0; }
        else if (t < 5)  { b = 1; loc = t - 1; }
        else if (t < 14) { b = 2; loc = t - 5; }
        else             { b = 3; loc = t - 14; }
        int s = c_SZ[b];
        int i = loc / s, j = loc - i * s;
        int ys = (i * 64) / s, ye = ((i + 1) * 64 + s - 1) / s;
        int xs = (j * 64) / s, xe = ((j + 1) * 64 + s - 1) / s;
        int rb = (b == 0) ? 0 : (b == 1) ? 64 : (b == 2) ? 192 : 384;
        float a = 0.f;
        for (int y = ys; y < ye; y++) a += rowp[rb + y * s + j];
        g_pool[c_PO[b] * 4096 + nc * c_S2[b] + loc] = a / (float)((ye - ys) * (xe - xs));
    }
}

// ----------------------- fused 1x1 convs: templated bodies, split-K 64
template <int S2>
__device__ __forceinline__ void conv1f_body(const float* __restrict__ W) {
    extern __shared__ float sm[];
    constexpr int C = 2 * S2;
    constexpr int Cp = C + 1;
    constexpr int PO = (S2 == 1) ? 0 : (S2 == 4) ? 1 : (S2 == 9) ? 5 : 14;
    constexpr int NA = (C + 3) / 4;
    float* pc = sm;
    float* ws = sm + 64 * Cp;
    int o0 = blockIdx.y * 64;
    int c0 = blockIdx.x * 64;
    int tid = threadIdx.x;
    int o = tid >> 2, grp = tid & 3;

    for (int i = tid; i < 64 * C; i += 256) {
        int c = i / C, col = i - c * C;
        int n = col / S2, ij = col - n * S2;
        pc[c * Cp + col] = g_pool[PO * 4096 + (n * 2048 + c0 + c) * S2 + ij];
    }
    for (int i = tid; i < 4096; i += 256) {
        int oo = i >> 6, k = i & 63;
        ws[oo * 65 + k] = W[(size_t)(o0 + oo) * 2048 + c0 + k];
    }
    __syncthreads();

    float acc[NA];
    #pragma unroll
    for (int a = 0; a < NA; a++) acc[a] = 0.f;
    for (int c = 0; c < 64; c++) {
        float w = ws[o * 65 + c];
        const float* pr = &pc[c * Cp];
        #pragma unroll
        for (int a = 0; a < NA; a++) {
            int col = grp + 4 * a;
            if (col < C) acc[a] += w * pr[col];
        }
    }
    #pragma unroll
    for (int a = 0; a < NA; a++) {
        int col = grp + 4 * a;
        if (col < C) {
            int n = col / S2, ij = col - n * S2;
            atomicAdd(&g_bo[PO * 1024 + (n * 512 + o0 + o) * S2 + ij], acc[a]);
        }
    }
}

__global__ void k_conv1f(const float* __restrict__ w0, const float* __restrict__ w1,
                         const float* __restrict__ w2, const float* __restrict__ w3) {
    switch (blockIdx.z) {
        case 0:  conv1f_body<1>(w0);  break;
        case 1:  conv1f_body<4>(w1);  break;
        case 2:  conv1f_body<9>(w2);  break;
        default: conv1f_body<36>(w3); break;
    }
}

// ---------------------------------------- per-branch BN + lrelu
__global__ void k_bnbr(const float* __restrict__ g0, const float* __restrict__ b0,
                       const float* __restrict__ g1, const float* __restrict__ b1,
                       const float* __restrict__ g2, const float* __restrict__ b2,
                       const float* __restrict__ g3, const float* __restrict__ b3) {
    int b = blockIdx.x >> 9, o = blockIdx.x & 511;
    int s2 = c_S2[b], cnt = 2 * s2;
    int tid = threadIdx.x;
    __shared__ float rs[128], rq[128];
    float v = 0.f; int idx = 0;
    if (tid < cnt) {
        int n = tid / s2, ij = tid - n * s2;
        idx = c_PO[b] * 1024 + (n * 512 + o) * s2 + ij;
        v = g_bo[idx];
    }
    rs[tid] = (tid < cnt) ? v : 0.f;
    rq[tid] = (tid < cnt) ? v * v : 0.f;
    __syncthreads();
    for (int st = 64; st > 0; st >>= 1) {
        if (tid < st) { rs[tid] += rs[tid + st]; rq[tid] += rq[tid + st]; }
        __syncthreads();
    }
    float mean = rs[0] / cnt, var = rq[0] / cnt - mean * mean;
    const float* gp = (b == 0) ? g0 : (b == 1) ? g1 : (b == 2) ? g2 : g3;
    const float* bp = (b == 0) ? b0 : (b == 1) ? b1 : (b == 2) ? b2 : b3;
    float sc = gp[o] * rsqrtf(var + EPS);
    float sh = bp[o] - mean * sc;
    if (tid < cnt) {
        float y = v * sc + sh;
        g_bhat[idx] = (y >= 0.f) ? y : SLOPE * y;
    }
}

// ===== fused q-GEMM + H-upsample + W-upsample -> g_v. block = one o (512). ==
#define QUPSV_SMEM (17408 * 4)
__global__ __launch_bounds__(512, 1) void k_qupsv(const float* __restrict__ wb) {
    extern __shared__ float sm[];
    float* ws = sm;
    float* bs = sm + 4608;
    int o = blockIdx.x;
    int tid = threadIdx.x;

    int tb, ttap = 0, tij = 0, ts2 = 1, tbase = 0;
    {
        int t = tid;
        if (t < 9)        { tb = 0; tbase = 0; }
        else if (t < 45)  { tb = 1; tbase = 9; }
        else if (t < 126) { tb = 2; tbase = 45; }
        else if (t < 450) { tb = 3; tbase = 126; }
        else              { tb = -1; }
        if (tb >= 0) {
            ts2 = c_S2[tb];
            int loc = t - tbase;
            ttap = loc / ts2; tij = loc - ttap * ts2;
        }
    }
    float acc0 = 0.f, acc1 = 0.f;
    const float* wrow = wb + (size_t)o * 36864;

    int bsOff[4] = {0, 256, 1280, 3584};
    for (int cc = 0; cc < 512; cc += 128) {
        __syncthreads();
        for (int i = tid; i < 4608; i += 512) {
            int b = (i < 1152) ? 0 : (i < 2304) ? 1 : (i < 3456) ? 2 : 3;
            int rr = i - b * 1152;
            ws[i] = wrow[b * 4608 + cc * 9 + rr];
        }
        for (int i = tid; i < 12800; i += 512) {
            int idx;
            if (i < 256) {
                int n = i >> 7, r = i & 127;
                idx = (n * 512 + cc + r);
            } else if (i < 1280) {
                int loc = i - 256;
                int n = loc >> 9, r = loc & 511;
                int c = r >> 2, ij = r & 3;
                idx = 1024 + (n * 512 + cc + c) * 4 + ij;
            } else if (i < 3584) {
                int loc = i - 1280;
                int n = loc / 1152, r = loc - n * 1152;
                int c = r / 9, ij = r - c * 9;
                idx = 5120 + (n * 512 + cc + c) * 9 + ij;
            } else {
                int loc = i - 3584;
                int n = loc / 4608, r = loc - n * 4608;
                int c = r / 36, ij = r - c * 36;
                idx = 14336 + (n * 512 + cc + c) * 36 + ij;
            }
            bs[i] = g_bhat[idx];
        }
        __syncthreads();
        if (tb >= 0) {
            const float* wv = &ws[tb * 1152 + ttap];
            const float* b0 = &bs[bsOff[tb] + tij];
            const float* b1 = b0 + 128 * ts2;
            #pragma unroll 8
            for (int c = 0; c < 128; c++) {
                float w = wv[c * 9];
                acc0 += w * b0[c * ts2];
                acc1 += w * b1[c * ts2];
            }
        }
    }
    __syncthreads();
    float* q2 = sm;
    float* u2 = sm + 1024;
    if (tb >= 0) {
        int qi = tbase + ttap * ts2 + tij;
        q2[qi] = acc0;
        q2[456 + qi] = acc1;
    }
    __syncthreads();

    for (int t = tid; t < 4608; t += 512) {
        int n = t / 2304, loc = t - n * 2304;
        int b, lb, ub;
        if (loc < 192)       { b = 0; lb = loc;        ub = 0; }
        else if (loc < 576)  { b = 1; lb = loc - 192;  ub = 192; }
        else if (loc < 1152) { b = 2; lb = loc - 576;  ub = 576; }
        else                 { b = 3; lb = loc - 1152; ub = 1152; }
        int s = c_SZ[b], s2 = c_S2[b];
        int kx = lb / (64 * s); int rem = lb - kx * 64 * s;
        int y = rem / s, j = rem - y * s;
        int qb = n * 456 + ((b == 0) ? 0 : (b == 1) ? 9 : (b == 2) ? 45 : 126);
        float fs = (s > 1) ? (float)(s - 1) / 63.0f : 0.0f;
        float a = 0.f;
        #pragma unroll
        for (int ky = 0; ky < 3; ky++) {
            int Y = y + ky - 1;
            if (Y < 0 || Y > 63) continue;
            float pos = Y * fs;
            int i0 = (int)pos; float w = pos - i0; int i1 = min(i0 + 1, s - 1);
            const float* qq = &q2[qb + (ky * 3 + kx) * s2 + j];
            a += (1.f - w) * qq[i0 * s] + w * qq[i1 * s];
        }
        u2[n * 2304 + ub + kx * 64 * s + y * s + j] = a;
    }
    __syncthreads();

    for (int t = tid; t < 8192; t += 512) {
        int n = t >> 12, px = t & 4095;
        int y = px >> 6, x = px & 63;
        float a = 0.f;
        #pragma unroll
        for (int b = 0; b < 4; b++) {
            int s = c_SZ[b];
            int ub = (b == 0) ? 0 : (b == 1) ? 192 : (b == 2) ? 576 : 1152;
            float fs = (s > 1) ? (float)(s - 1) / 63.f : 0.f;
            #pragma unroll
            for (int kx = 0; kx < 3; kx++) {
                int X = x + kx - 1;
                if (X < 0 || X > 63) continue;
                float pos = X * fs;
                int j0 = (int)pos; float w = pos - j0; int j1 = min(j0 + 1, s - 1);
                const float* uu = &u2[n * 2304 + ub + (kx * 64 + y) * s];
                a += (1.f - w) * uu[j0] + w * uu[j1];
            }
        }
        g_v[(((size_t)(n * 512 + o)) << 12) + px] = a;
    }
}

// ----------------- prep: weights -> fp16 half2 words, coalesced via smem
__global__ void k_prepW(const float* __restrict__ wb) {
    __shared__ float buf[32][148];
    int bx = blockIdx.x;
    int ot = bx >> 7, j = bx & 127;
    int tid = threadIdx.x;
    for (int g = 0; g < 4; g++) {
        __syncthreads();
        for (int i = tid; i < 1152; i += 512) {
            int ol = i / 36, f4 = i - ol * 36;
            const float4 v = *reinterpret_cast<const float4*>(
                wb + (size_t)(ot * 128 + g * 32 + ol) * 36864 + 18432 + j * 144 + f4 * 4);
            buf[ol][f4 * 4] = v.x; buf[ol][f4 * 4 + 1] = v.y;
            buf[ol][f4 * 4 + 2] = v.z; buf[ol][f4 * 4 + 3] = v.w;
        }
        __syncthreads();
        for (int i = tid; i < 2432; i += 512) {
            int ol = i / 76, r = i - ol * 76;
            uint32_t val = 0u;
            if (r < 72) {
                int tap = r >> 3, p = r & 7;
                __half2 h = __floats2half2_rn(buf[ol][2 * p * 9 + tap],
                                              buf[ol][(2 * p + 1) * 9 + tap]);
                val = *reinterpret_cast<uint32_t*>(&h);
            }
            g_wA[(size_t)bx * 9728 + (g * 32 + ol) * 76 + r] = val;
        }
    }
}

// ----------------- prep: patches -> fp16 half2 words [nb][chunk][pair 8][328]
__global__ void k_prepP(const float* __restrict__ feats) {
    int j = blockIdx.x;
    int nb = blockIdx.y;
    int n = nb >> 4, t = nb & 15;
    int ty0 = (t >> 2) * 16, tx0 = (t & 3) * 16;
    size_t dbase = (size_t)(nb * 128 + j) * 2624;
    for (int i = threadIdx.x; i < 2592; i += 512) {
        int p = i / 324, rr = i - p * 324;
        int y = rr / 18, x = rr - y * 18;
        int gy = ty0 + y - 1, gx = tx0 + x - 1;
        uint32_t val = 0u;
        if ((unsigned)gy < 64u && (unsigned)gx < 64u) {
            int c = j * 16 + 2 * p;
            const float* s = feats + (((size_t)(n * 2048 + c)) << 12) + (gy << 6) + gx;
            __half2 h = __floats2half2_rn(s[0], s[4096]);
            val = *reinterpret_cast<uint32_t*>(&h);
        }
        g_fB[dbase + p * 328 + rr] = val;
    }
}

// ======================= conv3x3: FP16 mma + ldmatrix, 3-stage, 1 barrier ==
#define ABYTES  38912u
#define PBYTES  10496u
#define STAGEB  49408u
#define NCP     3088
#define NCPA    2432
#define CONV_SMEM (3 * STAGEB)   // 148224

__global__ __launch_bounds__(512, 1) void k_conv3_h(float* __restrict__ out) {
    extern __shared__ char smem[];
    uint32_t sb = smem_u32(smem);
    int tid = threadIdx.x;
    int warp = tid >> 5, lane = tid & 31;
    int bx = blockIdx.x;
    int nb = blockIdx.y;
    int o0 = bx * 128;
    int n2 = nb >> 4;
    int t = nb & 15;
    int ty0 = (t >> 2) * 16, tx0 = (t & 3) * 16;
    int wm = warp >> 3, wn = warp & 7;
    int gid = lane >> 2, tig = lane & 3;
    int rsel = (lane & 8) + (lane & 7);
    int koff = (lane & 16) ? 4 : 0;

    float acc[4][4][4];
    #pragma unroll
    for (int mi = 0; mi < 4; mi++)
        #pragma unroll
        for (int ni = 0; ni < 4; ni++)
            #pragma unroll
            for (int r = 0; r < 4; r++) acc[mi][ni][r] = 0.f;

    int py[4], px[4];
    #pragma unroll
    for (int ni = 0; ni < 4; ni++) {
        int p = wn * 32 + ni * 8 + gid;
        py[ni] = p >> 4; px[ni] = p & 15;
    }

    const char* srcAbase = (const char*)(g_wA + (size_t)bx * 128 * 9728);
    const char* srcPbase = (const char*)(g_fB + (size_t)nb * 128 * 2624);

    auto stage = [&](int j) {
        uint32_t dA = sb + (j % 3) * STAGEB;
        uint32_t dP = dA + ABYTES;
        const char* sA = srcAbase + (size_t)j * ABYTES;
        const char* sP = srcPbase + (size_t)j * PBYTES;
        for (int i = tid; i < NCP; i += 512) {
            if (i < NCPA) cp16(dA + i * 16, sA + i * 16);
            else          cp16(dP + (i - NCPA) * 16, sP + (size_t)(i - NCPA) * 16);
        }
        cp_commit();
    };

    stage(0);
    stage(1);

    for (int j = 0; j < 128; j++) {
        if (j < 127) cp_wait<1>(); else cp_wait<0>();
        __syncthreads();   // single barrier: also orders prev-iter reads vs stage(j+2) overwrite
        if (j + 2 < 128) stage(j + 2);

        uint32_t aBase = sb + (j % 3) * STAGEB;
        const uint32_t* Ps = (const uint32_t*)(smem + (j % 3) * STAGEB + ABYTES);

        #pragma unroll
        for (int ky = 0; ky < 3; ky++) {
            #pragma unroll
            for (int kx = 0; kx < 3; kx++) {
                int tap8 = (ky * 3 + kx) * 8;
                uint32_t bf[4][2];
                #pragma unroll
                for (int ni = 0; ni < 4; ni++) {
                    int off = (py[ni] + ky) * 18 + px[ni] + kx;
                    bf[ni][0] = Ps[tig * 328 + off];
                    bf[ni][1] = Ps[(tig + 4) * 328 + off];
                }
                #pragma unroll
                for (int mi = 0; mi < 4; mi++) {
                    int m0 = wm * 64 + mi * 16;
                    uint32_t a0, a1, a2, a3;
                    ldsm4(a0, a1, a2, a3,
                          aBase + (uint32_t)(((m0 + rsel) * 76 + tap8 + koff) * 4));
                    #pragma unroll
                    for (int ni = 0; ni < 4; ni++)
                        mma16(acc[mi][ni], a0, a1, a2, a3, bf[ni][0], bf[ni][1]);
                }
            }
        }
    }

    // epilogue: store raw conv output (g_v folded into final BN)
    #pragma unroll
    for (int mi = 0; mi < 4; mi++) {
        int oa = o0 + wm * 64 + mi * 16 + gid;
        #pragma unroll
        for (int ni = 0; ni < 4; ni++) {
            int pA = wn * 32 + ni * 8 + 2 * tig;
            #pragma unroll
            for (int r = 0; r < 4; r++) {
                int o = oa + ((r >= 2) ? 8 : 0);
                int p = pA + (r & 1);
                int yy = ty0 + (p >> 4), xx = tx0 + (p & 15);
                size_t gi = (((size_t)(n2 * 512 + o)) << 12) + (yy << 6) + xx;
                out[gi] = acc[mi][ni][r];
            }
        }
    }
}

// --------------- fused final BN: per-channel stats + apply (z = out + g_v)
__global__ void k_bnfin(float* __restrict__ out, const float* __restrict__ gb,
                        const float* __restrict__ bbp) {
    int o = blockIdx.x;
    int tid = threadIdx.x;
    float s = 0.f, sq = 0.f;
    #pragma unroll
    for (int n = 0; n < 2; n++) {
        size_t base = ((size_t)(n * 512 + o)) << 10;
        const float4* p = (const float4*)out + base;
        const float4* pv = (const float4*)g_v + base;
        for (int i = tid; i < 1024; i += 256) {
            float4 a = p[i], b = pv[i];
            float v0 = a.x + b.x, v1 = a.y + b.y, v2 = a.z + b.z, v3 = a.w + b.w;
            s += v0 + v1 + v2 + v3;
            sq += v0 * v0 + v1 * v1 + v2 * v2 + v3 * v3;
        }
    }
    __shared__ float rs[256], rq[256];
    __shared__ float s_sc, s_sh;
    rs[tid] = s; rq[tid] = sq; __syncthreads();
    for (int st = 128; st > 0; st >>= 1) {
        if (tid < st) { rs[tid] += rs[tid + st]; rq[tid] += rq[tid + st]; }
        __syncthreads();
    }
    if (tid == 0) {
        float mean = rs[0] * (1.f / 8192.f);
        float var = rq[0] * (1.f / 8192.f) - mean * mean;
        float sc = gb[o] * rsqrtf(var + EPS);
        s_sc = sc;
        s_sh = bbp[o] - mean * sc;
    }
    __syncthreads();
    float sc = s_sc, sh = s_sh;
    #pragma unroll
    for (int n = 0; n < 2; n++) {
        size_t base = ((size_t)(n * 512 + o)) << 10;
        float4* p = (float4*)out + base;
        const float4* pv = (const float4*)g_v + base;
        for (int i = tid; i < 1024; i += 256) {
            float4 a = p[i], b = pv[i];
            float z0 = (a.x + b.x) * sc + sh;
            float z1 = (a.y + b.y) * sc + sh;
            float z2 = (a.z + b.z) * sc + sh;
            float z3 = (a.w + b.w) * sc + sh;
            float4 r;
            r.x = (z0 >= 0.f) ? z0 : SLOPE * z0;
            r.y = (z1 >= 0.f) ? z1 : SLOPE * z1;
            r.z = (z2 >= 0.f) ? z2 : SLOPE * z2;
            r.w = (z3 >= 0.f) ? z3 : SLOPE * z3;
            p[i] = r;
        }
    }
}

extern "C" void kernel_launch(void* const* d_in, const int* in_sizes, int n_in,
                              void* d_out, int out_size) {
    const float* feats = (const float*)d_in[0];
    const float* w0 = (const float*)d_in[1];
    const float* g0 = (const float*)d_in[2];
    const float* b0 = (const float*)d_in[3];
    const float* w1 = (const float*)d_in[4];
    const float* g1 = (const float*)d_in[5];
    const float* b1 = (const float*)d_in[6];
    const float* w2 = (const float*)d_in[7];
    const float* g2 = (const float*)d_in[8];
    const float* b2 = (const float*)d_in[9];
    const float* w3 = (const float*)d_in[10];
    const float* g3 = (const float*)d_in[11];
    const float* b3 = (const float*)d_in[12];
    const float* wb = (const float*)d_in[13];
    const float* gb = (const float*)d_in[14];
    const float* bb = (const float*)d_in[15];
    float* out = (float*)d_out;

    static cudaStream_t s2 = nullptr, s3 = nullptr;
    static cudaEvent_t evFork = nullptr, evP = nullptr, evJoin = nullptr;
    static bool init_done = false;
    if (!init_done) {
        cudaFuncSetAttribute(k_conv3_h, cudaFuncAttributeMaxDynamicSharedMemorySize, CONV_SMEM);
        cudaFuncSetAttribute(k_qupsv, cudaFuncAttributeMaxDynamicSharedMemorySize, QUPSV_SMEM);
        cudaFuncSetAttribute(k_conv1f, cudaFuncAttributeMaxDynamicSharedMemorySize, 36000);
        cudaStreamCreateWithFlags(&s2, cudaStreamNonBlocking);
        cudaStreamCreateWithFlags(&s3, cudaStreamNonBlocking);
        cudaEventCreateWithFlags(&evFork, cudaEventDisableTiming);
        cudaEventCreateWithFlags(&evP, cudaEventDisableTiming);
        cudaEventCreateWithFlags(&evJoin, cudaEventDisableTiming);
        init_done = true;
    }

    // Fork to s2 (prepP) and s3 (arm B)
    cudaEventRecord(evFork, 0);
    cudaStreamWaitEvent(s2, evFork, 0);
    cudaStreamWaitEvent(s3, evFork, 0);

    k_prepW<<<512, 512>>>(wb);                      // stream 0
    k_prepP<<<dim3(128, 32), 512, 0, s2>>>(feats);  // s2 (parallel with prepW)
    cudaEventRecord(evP, s2);

    k_pool<<<4096, 256, 0, s3>>>(feats);            // arm B on s3

    // conv3 waits on prepP (and prepW via stream order); launch #4 -> profiled
    cudaStreamWaitEvent(0, evP, 0);
    k_conv3_h<<<dim3(4, 32), 512, CONV_SMEM>>>(out);

    k_conv1f<<<dim3(32, 8, 4), 256, 35400, s3>>>(w0, w1, w2, w3);
    k_bnbr<<<2048, 128, 0, s3>>>(g0, b0, g1, b1, g2, b2, g3, b3);
    k_qupsv<<<512, 512, QUPSV_SMEM, s3>>>(wb);
    cudaEventRecord(evJoin, s3);

    // Join, then fused BN (stats + apply in one kernel)
    cudaStreamWaitEvent(0, evJoin, 0);
    k_bnfin<<<512, 256>>>(out, gb, bb);
}

// round 16
// speedup vs baseline: 1.0344x; 1.0087x over previous
#include <cuda_runtime.h>
#include <cuda_fp16.h>
#include <cstdint>

#define EPS   1e-5f
#define SLOPE 0.01f

__constant__ int c_SZ[4] = {1, 2, 3, 6};
__constant__ int c_S2[4] = {1, 4, 9, 36};
__constant__ int c_PO[4] = {0, 1, 5, 14};

// scratch (static device globals; no allocation)
__device__ float g_pool[204800];
__device__ float g_bo[51200];
__device__ float g_bhat[51200];
__device__ float g_v[4194304];
// pre-swizzled FP16 operands (32-bit words = half2 of channel pairs)
__device__ uint32_t g_wA[4980736];    // [4 ot][128 chunk][128 o][76 words]
__device__ uint32_t g_fB[10747904];   // [32 nb][128 chunk][spatial 324][pair 8]

// ---------------------------------------------------------------- helpers
__device__ __forceinline__ uint32_t smem_u32(const void* p) {
    uint32_t a;
    asm("{ .reg .u64 t; cvta.to.shared.u64 t, %1; cvt.u32.u64 %0, t; }" : "=r"(a) : "l"(p));
    return a;
}
__device__ __forceinline__ void cp16(uint32_t dst, const void* src) {
    asm volatile("cp.async.cg.shared.global [%0], [%1], 16;" :: "r"(dst), "l"(src));
}
__device__ __forceinline__ void cp_commit() {
    asm volatile("cp.async.commit_group;" ::: "memory");
}
template <int N> __device__ __forceinline__ void cp_wait() {
    asm volatile("cp.async.wait_group %0;" :: "n"(N) : "memory");
}
__device__ __forceinline__ void mma16(float* c, uint32_t a0, uint32_t a1, uint32_t a2, uint32_t a3,
                                      uint32_t b0, uint32_t b1) {
    asm volatile("mma.sync.aligned.m16n8k16.row.col.f32.f16.f16.f32 "
                 "{%0,%1,%2,%3}, {%4,%5,%6,%7}, {%8,%9}, {%0,%1,%2,%3};\n"
                 : "+f"(c[0]), "+f"(c[1]), "+f"(c[2]), "+f"(c[3])
                 : "r"(a0), "r"(a1), "r"(a2), "r"(a3), "r"(b0), "r"(b1));
}
__device__ __forceinline__ void ldsm4(uint32_t& r0, uint32_t& r1, uint32_t& r2, uint32_t& r3,
                                      uint32_t addr) {
    asm volatile("ldmatrix.sync.aligned.m8n8.x4.shared.b16 {%0,%1,%2,%3}, [%4];"
                 : "=r"(r0), "=r"(r1), "=r"(r2), "=r"(r3) : "r"(addr));
}

// ------------------- pools via row prefix sums (+ zero g_bo in blocks <50)
__global__ void k_pool(const float* __restrict__ feats) {
    __shared__ float S[64][65];
    __shared__ float rowp[768];
    int nc = blockIdx.x;
    int tid = threadIdx.x;
    if (nc < 50) {
        for (int i = tid; i < 1024; i += 256) g_bo[nc * 1024 + i] = 0.f;
    }
    const float* src = feats + (size_t)nc * 4096;
    int warp = tid >> 5, lane = tid & 31;
    #pragma unroll
    for (int k = 0; k < 8; k++) {
        int y = warp * 8 + k;
        float v = src[y * 64 + lane];
        #pragma unroll
        for (int off = 1; off < 32; off <<= 1) {
            float n = __shfl_up_sync(0xffffffffu, v, off);
            if (lane >= off) v += n;
        }
        float tot = __shfl_sync(0xffffffffu, v, 31);
        float w = src[y * 64 + 32 + lane];
        #pragma unroll
        for (int off = 1; off < 32; off <<= 1) {
            float n = __shfl_up_sync(0xffffffffu, w, off);
            if (lane >= off) w += n;
        }
        S[y][lane + 1] = v;
        S[y][lane + 33] = w + tot;
        if (lane == 0) S[y][0] = 0.f;
    }
    __syncthreads();
    for (int t = tid; t < 768; t += 256) {
        int b, loc;
        if (t < 64)       { b = 0; loc = t; }
        else if (t < 192) { b = 1; loc = t - 64; }
        else if (t < 384) { b = 2; loc = t - 192; }
        else              { b = 3; loc = t - 384; }
        int s = c_SZ[b];
        int y = loc / s, j = loc - y * s;
        int xs = (j * 64) / s, xe = ((j + 1) * 64 + s - 1) / s;
        rowp[t] = S[y][xe] - S[y][xs];
    }
    __syncthreads();
    if (tid < 50) {
        int t = tid; int b, loc;
        if (t < 1)       { b = 0; loc = 0; }
        else if (t < 5)  { b = 1; loc = t - 1; }
        else if (t < 14) { b = 2; loc = t - 5; }
        else             { b = 3; loc = t - 14; }
        int s = c_SZ[b];
        int i = loc / s, j = loc - i * s;
        int ys = (i * 64) / s, ye = ((i + 1) * 64 + s - 1) / s;
        int xs = (j * 64) / s, xe = ((j + 1) * 64 + s - 1) / s;
        int rb = (b == 0) ? 0 : (b == 1) ? 64 : (b == 2) ? 192 : 384;
        float a = 0.f;
        for (int y = ys; y < ye; y++) a += rowp[rb + y * s + j];
        g_pool[c_PO[b] * 4096 + nc * c_S2[b] + loc] = a / (float)((ye - ys) * (xe - xs));
    }
}

// ----------------------- fused 1x1 convs: templated bodies, split-K 64
template <int S2>
__device__ __forceinline__ void conv1f_body(const float* __restrict__ W) {
    extern __shared__ float sm[];
    constexpr int C = 2 * S2;
    constexpr int Cp = C + 1;
    constexpr int PO = (S2 == 1) ? 0 : (S2 == 4) ? 1 : (S2 == 9) ? 5 : 14;
    constexpr int NA = (C + 3) / 4;
    float* pc = sm;
    float* ws = sm + 64 * Cp;
    int o0 = blockIdx.y * 64;
    int c0 = blockIdx.x * 64;
    int tid = threadIdx.x;
    int o = tid >> 2, grp = tid & 3;

    for (int i = tid; i < 64 * C; i += 256) {
        int c = i / C, col = i - c * C;
        int n = col / S2, ij = col - n * S2;
        pc[c * Cp + col] = g_pool[PO * 4096 + (n * 2048 + c0 + c) * S2 + ij];
    }
    for (int i = tid; i < 4096; i += 256) {
        int oo = i >> 6, k = i & 63;
        ws[oo * 65 + k] = W[(size_t)(o0 + oo) * 2048 + c0 + k];
    }
    __syncthreads();

    float acc[NA];
    #pragma unroll
    for (int a = 0; a < NA; a++) acc[a] = 0.f;
    for (int c = 0; c < 64; c++) {
        float w = ws[o * 65 + c];
        const float* pr = &pc[c * Cp];
        #pragma unroll
        for (int a = 0; a < NA; a++) {
            int col = grp + 4 * a;
            if (col < C) acc[a] += w * pr[col];
        }
    }
    #pragma unroll
    for (int a = 0; a < NA; a++) {
        int col = grp + 4 * a;
        if (col < C) {
            int n = col / S2, ij = col - n * S2;
            atomicAdd(&g_bo[PO * 1024 + (n * 512 + o0 + o) * S2 + ij], acc[a]);
        }
    }
}

__global__ void k_conv1f(const float* __restrict__ w0, const float* __restrict__ w1,
                         const float* __restrict__ w2, const float* __restrict__ w3) {
    switch (blockIdx.z) {
        case 0:  conv1f_body<1>(w0);  break;
        case 1:  conv1f_body<4>(w1);  break;
        case 2:  conv1f_body<9>(w2);  break;
        default: conv1f_body<36>(w3); break;
    }
}

// ---------------------------------------- per-branch BN + lrelu
__global__ void k_bnbr(const float* __restrict__ g0, const float* __restrict__ b0,
                       const float* __restrict__ g1, const float* __restrict__ b1,
                       const float* __restrict__ g2, const float* __restrict__ b2,
                       const float* __restrict__ g3, const float* __restrict__ b3) {
    int b = blockIdx.x >> 9, o = blockIdx.x & 511;
    int s2 = c_S2[b], cnt = 2 * s2;
    int tid = threadIdx.x;
    __shared__ float rs[128], rq[128];
    float v = 0.f; int idx = 0;
    if (tid < cnt) {
        int n = tid / s2, ij = tid - n * s2;
        idx = c_PO[b] * 1024 + (n * 512 + o) * s2 + ij;
        v = g_bo[idx];
    }
    rs[tid] = (tid < cnt) ? v : 0.f;
    rq[tid] = (tid < cnt) ? v * v : 0.f;
    __syncthreads();
    for (int st = 64; st > 0; st >>= 1) {
        if (tid < st) { rs[tid] += rs[tid + st]; rq[tid] += rq[tid + st]; }
        __syncthreads();
    }
    float mean = rs[0] / cnt, var = rq[0] / cnt - mean * mean;
    const float* gp = (b == 0) ? g0 : (b == 1) ? g1 : (b == 2) ? g2 : g3;
    const float* bp = (b == 0) ? b0 : (b == 1) ? b1 : (b == 2) ? b2 : b3;
    float sc = gp[o] * rsqrtf(var + EPS);
    float sh = bp[o] - mean * sc;
    if (tid < cnt) {
        float y = v * sc + sh;
        g_bhat[idx] = (y >= 0.f) ? y : SLOPE * y;
    }
}

// ===== fused q-GEMM + H-upsample + W-upsample -> g_v. block = one o (512). ==
#define QUPSV_SMEM (17408 * 4)
__global__ __launch_bounds__(512, 1) void k_qupsv(const float* __restrict__ wb) {
    extern __shared__ float sm[];
    float* ws = sm;
    float* bs = sm + 4608;
    int o = blockIdx.x;
    int tid = threadIdx.x;

    int tb, ttap = 0, tij = 0, ts2 = 1, tbase = 0;
    {
        int t = tid;
        if (t < 9)        { tb = 0; tbase = 0; }
        else if (t < 45)  { tb = 1; tbase = 9; }
        else if (t < 126) { tb = 2; tbase = 45; }
        else if (t < 450) { tb = 3; tbase = 126; }
        else              { tb = -1; }
        if (tb >= 0) {
            ts2 = c_S2[tb];
            int loc = t - tbase;
            ttap = loc / ts2; tij = loc - ttap * ts2;
        }
    }
    float acc0 = 0.f, acc1 = 0.f;
    const float* wrow = wb + (size_t)o * 36864;

    int bsOff[4] = {0, 256, 1280, 3584};
    for (int cc = 0; cc < 512; cc += 128) {
        __syncthreads();
        for (int i = tid; i < 4608; i += 512) {
            int b = (i < 1152) ? 0 : (i < 2304) ? 1 : (i < 3456) ? 2 : 3;
            int rr = i - b * 1152;
            ws[i] = wrow[b * 4608 + cc * 9 + rr];
        }
        for (int i = tid; i < 12800; i += 512) {
            int idx;
            if (i < 256) {
                int n = i >> 7, r = i & 127;
                idx = (n * 512 + cc + r);
            } else if (i < 1280) {
                int loc = i - 256;
                int n = loc >> 9, r = loc & 511;
                int c = r >> 2, ij = r & 3;
                idx = 1024 + (n * 512 + cc + c) * 4 + ij;
            } else if (i < 3584) {
                int loc = i - 1280;
                int n = loc / 1152, r = loc - n * 1152;
                int c = r / 9, ij = r - c * 9;
                idx = 5120 + (n * 512 + cc + c) * 9 + ij;
            } else {
                int loc = i - 3584;
                int n = loc / 4608, r = loc - n * 4608;
                int c = r / 36, ij = r - c * 36;
                idx = 14336 + (n * 512 + cc + c) * 36 + ij;
            }
            bs[i] = g_bhat[idx];
        }
        __syncthreads();
        if (tb >= 0) {
            const float* wv = &ws[tb * 1152 + ttap];
            const float* b0 = &bs[bsOff[tb] + tij];
            const float* b1 = b0 + 128 * ts2;
            #pragma unroll 8
            for (int c = 0; c < 128; c++) {
                float w = wv[c * 9];
                acc0 += w * b0[c * ts2];
                acc1 += w * b1[c * ts2];
            }
        }
    }
    __syncthreads();
    float* q2 = sm;
    float* u2 = sm + 1024;
    if (tb >= 0) {
        int qi = tbase + ttap * ts2 + tij;
        q2[qi] = acc0;
        q2[456 + qi] = acc1;
    }
    __syncthreads();

    for (int t = tid; t < 4608; t += 512) {
        int n = t / 2304, loc = t - n * 2304;
        int b, lb, ub;
        if (loc < 192)       { b = 0; lb = loc;        ub = 0; }
        else if (loc < 576)  { b = 1; lb = loc - 192;  ub = 192; }
        else if (loc < 1152) { b = 2; lb = loc - 576;  ub = 576; }
        else                 { b = 3; lb = loc - 1152; ub = 1152; }
        int s = c_SZ[b], s2 = c_S2[b];
        int kx = lb / (64 * s); int rem = lb - kx * 64 * s;
        int y = rem / s, j = rem - y * s;
        int qb = n * 456 + ((b == 0) ? 0 : (b == 1) ? 9 : (b == 2) ? 45 : 126);
        float fs = (s > 1) ? (float)(s - 1) / 63.0f : 0.0f;
        float a = 0.f;
        #pragma unroll
        for (int ky = 0; ky < 3; ky++) {
            int Y = y + ky - 1;
            if (Y < 0 || Y > 63) continue;
            float pos = Y * fs;
            int i0 = (int)pos; float w = pos - i0; int i1 = min(i0 + 1, s - 1);
            const float* qq = &q2[qb + (ky * 3 + kx) * s2 + j];
            a += (1.f - w) * qq[i0 * s] + w * qq[i1 * s];
        }
        u2[n * 2304 + ub + kx * 64 * s + y * s + j] = a;
    }
    __syncthreads();

    for (int t = tid; t < 8192; t += 512) {
        int n = t >> 12, px = t & 4095;
        int y = px >> 6, x = px & 63;
        float a = 0.f;
        #pragma unroll
        for (int b = 0; b < 4; b++) {
            int s = c_SZ[b];
            int ub = (b == 0) ? 0 : (b == 1) ? 192 : (b == 2) ? 576 : 1152;
            float fs = (s > 1) ? (float)(s - 1) / 63.f : 0.f;
            #pragma unroll
            for (int kx = 0; kx < 3; kx++) {
                int X = x + kx - 1;
                if (X < 0 || X > 63) continue;
                float pos = X * fs;
                int j0 = (int)pos; float w = pos - j0; int j1 = min(j0 + 1, s - 1);
                const float* uu = &u2[n * 2304 + ub + (kx * 64 + y) * s];
                a += (1.f - w) * uu[j0] + w * uu[j1];
            }
        }
        g_v[(((size_t)(n * 512 + o)) << 12) + px] = a;
    }
}

// ----------------- prep: weights -> fp16 half2 words, coalesced via smem
__global__ void k_prepW(const float* __restrict__ wb) {
    __shared__ float buf[32][148];
    int bx = blockIdx.x;
    int ot = bx >> 7, j = bx & 127;
    int tid = threadIdx.x;
    for (int g = 0; g < 4; g++) {
        __syncthreads();
        for (int i = tid; i < 1152; i += 512) {
            int ol = i / 36, f4 = i - ol * 36;
            const float4 v = *reinterpret_cast<const float4*>(
                wb + (size_t)(ot * 128 + g * 32 + ol) * 36864 + 18432 + j * 144 + f4 * 4);
            buf[ol][f4 * 4] = v.x; buf[ol][f4 * 4 + 1] = v.y;
            buf[ol][f4 * 4 + 2] = v.z; buf[ol][f4 * 4 + 3] = v.w;
        }
        __syncthreads();
        for (int i = tid; i < 2432; i += 512) {
            int ol = i / 76, r = i - ol * 76;
            uint32_t val = 0u;
            if (r < 72) {
                int tap = r >> 3, p = r & 7;
                __half2 h = __floats2half2_rn(buf[ol][2 * p * 9 + tap],
                                              buf[ol][(2 * p + 1) * 9 + tap]);
                val = *reinterpret_cast<uint32_t*>(&h);
            }
            g_wA[(size_t)bx * 9728 + (g * 32 + ol) * 76 + r] = val;
        }
    }
}

// ----------------- prep: patches, pair-interleaved [spatial 324][perm-pair 8]
// perm[p] = (p<4) ? 2p : 2(p-4)+1 so (pair t, pair t+4) are adjacent words.
__global__ void k_prepP(const float* __restrict__ feats) {
    __shared__ uint32_t tbuf[2592];
    int j = blockIdx.x;
    int nb = blockIdx.y;
    int n = nb >> 4, t = nb & 15;
    int ty0 = (t >> 2) * 16, tx0 = (t & 3) * 16;
    for (int i = threadIdx.x; i < 2592; i += 512) {
        int p = i / 324, rr = i - p * 324;
        int y = rr / 18, x = rr - y * 18;
        int gy = ty0 + y - 1, gx = tx0 + x - 1;
        uint32_t val = 0u;
        if ((unsigned)gy < 64u && (unsigned)gx < 64u) {
            int c = j * 16 + 2 * p;
            const float* s = feats + (((size_t)(n * 2048 + c)) << 12) + (gy << 6) + gx;
            __half2 h = __floats2half2_rn(s[0], s[4096]);
            val = *reinterpret_cast<uint32_t*>(&h);
        }
        int perm = (p < 4) ? 2 * p : 2 * (p - 4) + 1;
        tbuf[rr * 8 + perm] = val;
    }
    __syncthreads();
    size_t dbase = (size_t)(nb * 128 + j) * 2592;
    for (int i = threadIdx.x; i < 2592; i += 512)
        g_fB[dbase + i] = tbuf[i];
}

// ======================= conv3x3: FP16 mma + ldmatrix, LDS.64 B frags ======
#define ABYTES  38912u
#define PBYTES  10368u       // 324 spatial * 8 pairs * 4B
#define STAGEB  49280u
#define NCP     3080
#define NCPA    2432
#define CONV_SMEM (3 * STAGEB)   // 147840

__global__ __launch_bounds__(512, 1) void k_conv3_h(float* __restrict__ out) {
    extern __shared__ char smem[];
    uint32_t sb = smem_u32(smem);
    int tid = threadIdx.x;
    int warp = tid >> 5, lane = tid & 31;
    int bx = blockIdx.x;
    int nb = blockIdx.y;
    int o0 = bx * 128;
    int n2 = nb >> 4;
    int t = nb & 15;
    int ty0 = (t >> 2) * 16, tx0 = (t & 3) * 16;
    int wm = warp >> 3, wn = warp & 7;
    int gid = lane >> 2, tig = lane & 3;
    int rsel = (lane & 8) + (lane & 7);
    int koff = (lane & 16) ? 4 : 0;

    float acc[4][4][4];
    #pragma unroll
    for (int mi = 0; mi < 4; mi++)
        #pragma unroll
        for (int ni = 0; ni < 4; ni++)
            #pragma unroll
            for (int r = 0; r < 4; r++) acc[mi][ni][r] = 0.f;

    int py[4], px[4];
    #pragma unroll
    for (int ni = 0; ni < 4; ni++) {
        int p = wn * 32 + ni * 8 + gid;
        py[ni] = p >> 4; px[ni] = p & 15;
    }

    const char* srcAbase = (const char*)(g_wA + (size_t)bx * 128 * 9728);
    const char* srcPbase = (const char*)(g_fB + (size_t)nb * 128 * 2592);

    auto stage = [&](int j) {
        uint32_t dA = sb + (j % 3) * STAGEB;
        uint32_t dP = dA + ABYTES;
        const char* sA = srcAbase + (size_t)j * ABYTES;
        const char* sP = srcPbase + (size_t)j * PBYTES;
        for (int i = tid; i < NCP; i += 512) {
            if (i < NCPA) cp16(dA + i * 16, sA + i * 16);
            else          cp16(dP + (i - NCPA) * 16, sP + (size_t)(i - NCPA) * 16);
        }
        cp_commit();
    };

    stage(0);
    stage(1);

    for (int j = 0; j < 128; j++) {
        if (j < 127) cp_wait<1>(); else cp_wait<0>();
        __syncthreads();   // single barrier: orders prev-iter reads vs stage(j+2) overwrite
        if (j + 2 < 128) stage(j + 2);

        uint32_t aBase = sb + (j % 3) * STAGEB;
        const uint32_t* Ps = (const uint32_t*)(smem + (j % 3) * STAGEB + ABYTES);

        #pragma unroll
        for (int ky = 0; ky < 3; ky++) {
            #pragma unroll
            for (int kx = 0; kx < 3; kx++) {
                int tap8 = (ky * 3 + kx) * 8;
                uint32_t bf[4][2];
                #pragma unroll
                for (int ni = 0; ni < 4; ni++) {
                    int off = (py[ni] + ky) * 18 + px[ni] + kx;
                    uint2 bv = *reinterpret_cast<const uint2*>(Ps + off * 8 + 2 * tig);
                    bf[ni][0] = bv.x;
                    bf[ni][1] = bv.y;
                }
                #pragma unroll
                for (int mi = 0; mi < 4; mi++) {
                    int m0 = wm * 64 + mi * 16;
                    uint32_t a0, a1, a2, a3;
                    ldsm4(a0, a1, a2, a3,
                          aBase + (uint32_t)(((m0 + rsel) * 76 + tap8 + koff) * 4));
                    #pragma unroll
                    for (int ni = 0; ni < 4; ni++)
                        mma16(acc[mi][ni], a0, a1, a2, a3, bf[ni][0], bf[ni][1]);
                }
            }
        }
    }

    // epilogue: float2 stores of raw conv output (g_v folded into final BN)
    #pragma unroll
    for (int mi = 0; mi < 4; mi++) {
        int oa = o0 + wm * 64 + mi * 16 + gid;
        #pragma unroll
        for (int ni = 0; ni < 4; ni++) {
            int pA = wn * 32 + ni * 8 + 2 * tig;
            int yy = ty0 + (pA >> 4), xx = tx0 + (pA & 15);
            size_t gi0 = (((size_t)(n2 * 512 + oa)) << 12) + (yy << 6) + xx;
            size_t gi1 = (((size_t)(n2 * 512 + oa + 8)) << 12) + (yy << 6) + xx;
            float2 v0 = make_float2(acc[mi][ni][0], acc[mi][ni][1]);
            float2 v1 = make_float2(acc[mi][ni][2], acc[mi][ni][3]);
            *reinterpret_cast<float2*>(out + gi0) = v0;
            *reinterpret_cast<float2*>(out + gi1) = v1;
        }
    }
}

// --------------- fused final BN: per-channel stats + apply (z = out + g_v)
__global__ void k_bnfin(float* __restrict__ out, const float* __restrict__ gb,
                        const float* __restrict__ bbp) {
    int o = blockIdx.x;
    int tid = threadIdx.x;
    float s = 0.f, sq = 0.f;
    #pragma unroll
    for (int n = 0; n < 2; n++) {
        size_t base = ((size_t)(n * 512 + o)) << 10;
        const float4* p = (const float4*)out + base;
        const float4* pv = (const float4*)g_v + base;
        for (int i = tid; i < 1024; i += 256) {
            float4 a = p[i], b = pv[i];
            float v0 = a.x + b.x, v1 = a.y + b.y, v2 = a.z + b.z, v3 = a.w + b.w;
            s += v0 + v1 + v2 + v3;
            sq += v0 * v0 + v1 * v1 + v2 * v2 + v3 * v3;
        }
    }
    __shared__ float rs[256], rq[256];
    __shared__ float s_sc, s_sh;
    rs[tid] = s; rq[tid] = sq; __syncthreads();
    for (int st = 128; st > 0; st >>= 1) {
        if (tid < st) { rs[tid] += rs[tid + st]; rq[tid] += rq[tid + st]; }
        __syncthreads();
    }
    if (tid == 0) {
        float mean = rs[0] * (1.f / 8192.f);
        float var = rq[0] * (1.f / 8192.f) - mean * mean;
        float sc = gb[o] * rsqrtf(var + EPS);
        s_sc = sc;
        s_sh = bbp[o] - mean * sc;
    }
    __syncthreads();
    float sc = s_sc, sh = s_sh;
    #pragma unroll
    for (int n = 0; n < 2; n++) {
        size_t base = ((size_t)(n * 512 + o)) << 10;
        float4* p = (float4*)out + base;
        const float4* pv = (const float4*)g_v + base;
        for (int i = tid; i < 1024; i += 256) {
            float4 a = p[i], b = pv[i];
            float z0 = (a.x + b.x) * sc + sh;
            float z1 = (a.y + b.y) * sc + sh;
            float z2 = (a.z + b.z) * sc + sh;
            float z3 = (a.w + b.w) * sc + sh;
            float4 r;
            r.x = (z0 >= 0.f) ? z0 : SLOPE * z0;
            r.y = (z1 >= 0.f) ? z1 : SLOPE * z1;
            r.z = (z2 >= 0.f) ? z2 : SLOPE * z2;
            r.w = (z3 >= 0.f) ? z3 : SLOPE * z3;
            p[i] = r;
        }
    }
}

extern "C" void kernel_launch(void* const* d_in, const int* in_sizes, int n_in,
                              void* d_out, int out_size) {
    const float* feats = (const float*)d_in[0];
    const float* w0 = (const float*)d_in[1];
    const float* g0 = (const float*)d_in[2];
    const float* b0 = (const float*)d_in[3];
    const float* w1 = (const float*)d_in[4];
    const float* g1 = (const float*)d_in[5];
    const float* b1 = (const float*)d_in[6];
    const float* w2 = (const float*)d_in[7];
    const float* g2 = (const float*)d_in[8];
    const float* b2 = (const float*)d_in[9];
    const float* w3 = (const float*)d_in[10];
    const float* g3 = (const float*)d_in[11];
    const float* b3 = (const float*)d_in[12];
    const float* wb = (const float*)d_in[13];
    const float* gb = (const float*)d_in[14];
    const float* bb = (const float*)d_in[15];
    float* out = (float*)d_out;

    static cudaStream_t s2 = nullptr, s3 = nullptr;
    static cudaEvent_t evFork = nullptr, evP = nullptr, evJoin = nullptr;
    static bool init_done = false;
    if (!init_done) {
        cudaFuncSetAttribute(k_conv3_h, cudaFuncAttributeMaxDynamicSharedMemorySize, CONV_SMEM);
        cudaFuncSetAttribute(k_qupsv, cudaFuncAttributeMaxDynamicSharedMemorySize, QUPSV_SMEM);
        cudaFuncSetAttribute(k_conv1f, cudaFuncAttributeMaxDynamicSharedMemorySize, 36000);
        cudaStreamCreateWithFlags(&s2, cudaStreamNonBlocking);
        cudaStreamCreateWithFlags(&s3, cudaStreamNonBlocking);
        cudaEventCreateWithFlags(&evFork, cudaEventDisableTiming);
        cudaEventCreateWithFlags(&evP, cudaEventDisableTiming);
        cudaEventCreateWithFlags(&evJoin, cudaEventDisableTiming);
        init_done = true;
    }

    // Fork to s2 (prepP) and s3 (arm B)
    cudaEventRecord(evFork, 0);
    cudaStreamWaitEvent(s2, evFork, 0);
    cudaStreamWaitEvent(s3, evFork, 0);

    k_prepW<<<512, 512>>>(wb);                      // stream 0
    k_prepP<<<dim3(128, 32), 512, 0, s2>>>(feats);  // s2 (parallel with prepW)
    cudaEventRecord(evP, s2);

    k_pool<<<4096, 256, 0, s3>>>(feats);            // arm B on s3

    // conv3 waits on prepP (and prepW via stream order); launch #4 -> profiled
    cudaStreamWaitEvent(0, evP, 0);
    k_conv3_h<<<dim3(4, 32), 512, CONV_SMEM>>>(out);

    k_conv1f<<<dim3(32, 8, 4), 256, 35400, s3>>>(w0, w1, w2, w3);
    k_bnbr<<<2048, 128, 0, s3>>>(g0, b0, g1, b1, g2, b2, g3, b3);
    k_qupsv<<<512, 512, QUPSV_SMEM, s3>>>(wb);
    cudaEventRecord(evJoin, s3);

    // Join, then fused BN (stats + apply in one kernel)
    cudaStreamWaitEvent(0, evJoin, 0);
    k_bnfin<<<512, 256>>>(out, gb, bb);
}